// round 16
// baseline (speedup 1.0000x reference)
#include <cuda_runtime.h>
#include <cuda_bf16.h>
#include <cstdint>

// ---------------------------------------------------------------------------
// SpatialNonIntersectionAxiom — serial 3-node graph:
//   memset(planes) -> prep(block-aggregated batching) -> compute(row-pair
//   tiled pair math; last block scatters violations, writes out[0], and
//   self-resets bookkeeping for the next graph replay).
// out[0]=loss, out[1..1+E^2)=violation_mask, out[1+E^2..1+2E^2)=scores (f32).
// Integer fixed-point (2^-40) totals + value-pure scatter to distinct cells
// -> bit-deterministic outputs across replays (list/table order may vary).
// Rules learned: no warp collectives in non-uniform loops; no SM-level
// overlap of fill with compute; driver memset only for the big planes.
// ---------------------------------------------------------------------------

#define MAXE  8192
#define MAXB  16
#define BLK   256
#define CHNK  96
#define SMAXL 768
#define VCAP  (1024 * 1024)

// Batch-major per-edge tables (__device__: no allocs allowed)
__device__ float4 g_tP[MAXB * MAXE]; // psx, psy, d1x, d1y
__device__ float4 g_tM[MAXB * MAXE]; // midx, midy, hh=half+0.075, packed(s<<12|d)
__device__ float4 g_tD[MAXB * MAXE]; // dda, sq(clamped), rinv=1/sq, edgeIdx bits
__device__ uint2  g_viol[VCAP];      // x = (i<<12)|j, y = pl bits

struct Bookkeep {
    unsigned long long totQ;   // fixed-point 2^-40 loss sum
    unsigned long long totC;   // candidate count (n_pairs)
    unsigned int nViol;        // violation list length
    unsigned int done;         // finished-block counter
    int bcnt[MAXB];            // per-batch table lengths
};
__device__ Bookkeep g_bk;      // statically zero-initialized; self-resetting

__global__ void __launch_bounds__(BLK)
prep_kernel(const float* __restrict__ pos, const int* __restrict__ ei,
            int E, int N, int nodes) {
    __shared__ int scnt[MAXB];
    __shared__ int sbase[MAXB];
    if (threadIdx.x < MAXB) scnt[threadIdx.x] = 0;
    __syncthreads();

    int e = blockIdx.x * blockDim.x + threadIdx.x;
    int b = 0, lslot = 0, s = 0, d = 0;
    bool valid = (e < E);
    if (valid) {
        s = min(max(ei[e], 0), nodes - 1);
        d = min(max(ei[E + e], 0), nodes - 1);
        b = min(s / N, MAXB - 1);
        lslot = atomicAdd(&scnt[b], 1);          // smem atomic: cheap
    }
    __syncthreads();
    if (threadIdx.x < MAXB)                       // 1 global atomic per batch
        sbase[threadIdx.x] = atomicAdd(&g_bk.bcnt[threadIdx.x],
                                       scnt[threadIdx.x]);
    __syncthreads();

    if (valid) {
        int p = sbase[b] + lslot;
        if (p < MAXE) {
            float psx = pos[2 * s], psy = pos[2 * s + 1];
            float pdx = pos[2 * d], pdy = pos[2 * d + 1];
            float d1x = pdx - psx,  d1y = pdy - psy;
            float rawsq = d1x * d1x + d1y * d1y;
            float sq    = fmaxf(rawsq, 1e-12f);
            float rinv  = __fdiv_rn(1.0f, sq);
            float half  = __fsqrt_rn(rawsq) * 0.5f;
            unsigned int packed = (((unsigned int)s & 0xFFFu) << 12)
                                | ((unsigned int)d & 0xFFFu);
            int o = b * MAXE + p;
            g_tP[o] = make_float4(psx, psy, d1x, d1y);
            g_tM[o] = make_float4((psx + pdx) * 0.5f, (psy + pdy) * 0.5f,
                                  half + 0.075f, __uint_as_float(packed));
            g_tD[o] = make_float4(d1x * psx + d1y * psy, sq, rinv,
                                  __int_as_float(e));
        }
    }
}

// One ordered pair (i<j orientation via sw), reference clamp order.
// Returns pl (0 if not violating); increments *cnt if candidate-mask true.
__device__ __forceinline__ float pair_eval(
    const float4& rP, const float4& rM, const float4& rD, unsigned int pr,
    int re,
    const float4& qP, const float4& qM, const float4& qD, unsigned int pq,
    int qe, bool act, unsigned int* cnt, bool* swOut)
{
    unsigned int rs = pr >> 12, rd = pr & 0xFFFu;
    unsigned int qs = pq >> 12, qd = pq & 0xFFFu;
    bool shares = (rs == qs) | (rs == qd) | (rd == qs) | (rd == qd);
    float dx = rM.x - qM.x;
    float dy = rM.y - qM.y;
    float d2 = dx * dx + dy * dy;
    float reach = rM.z + qM.z;                    // half_i+half_j+0.15
    bool maskok = act && (!shares) && (d2 < reach * reach);
    *cnt += maskok ? 1u : 0u;

    bool sw = re > qe;                            // orient i = smaller edge
    *swOut = sw;
    float iAx = sw ? qP.x : rP.x, iAy = sw ? qP.y : rP.y;
    float iAz = sw ? qP.z : rP.z, iAw = sw ? qP.w : rP.w;
    float jAx = sw ? rP.x : qP.x, jAy = sw ? rP.y : qP.y;
    float jAz = sw ? rP.z : qP.z, jAw = sw ? rP.w : qP.w;
    float iDd = sw ? qD.x : rD.x, jDd = sw ? rD.x : qD.x;
    float A   = sw ? qD.y : rD.y, Ee  = sw ? rD.y : qD.y;
    float rA  = sw ? qD.z : rD.z, rE  = sw ? rD.z : qD.z;

    float bb = iAz * jAz + iAw * jAw;
    float cc = iDd - (iAz * jAx + iAw * jAy);
    float ff = (iAx * jAz + iAy * jAw) - jDd;
    float denom = fmaxf(A * Ee - bb * bb, 1e-12f);
    float s = (bb * ff - cc * Ee) * __frcp_rn(denom);
    s = fminf(fmaxf(s, 0.0f), 1.0f);
    float t = fminf(fmaxf((bb * s + ff) * rE, 0.0f), 1.0f);
    s = fminf(fmaxf((bb * t - cc) * rA, 0.0f), 1.0f);
    float cax = iAx + s * iAz;
    float cay = iAy + s * iAw;
    float cbx = jAx + t * jAz;
    float cby = jAy + t * jAw;
    float ddx = cax - cbx, ddy = cay - cby;
    float dmsq = ddx * ddx + ddy * ddy;

    float pl = 0.0f;
    if (maskok && dmsq < 1.01e-6f) {              // rare
        float dmin = __fsqrt_rn(dmsq);
        pl = fmaxf(0.001f - dmin, 0.0f);
    }
    return pl;
}

__device__ __forceinline__ void record_hit(
    float pl, bool sw, int re, int qe,
    unsigned long long* accQ)
{
    if (pl > 0.0f) {
        *accQ += (unsigned long long)
            __double2ll_rn((double)pl * 1099511627776.0);
        unsigned int pos = atomicAdd(&g_bk.nViol, 1u);  // rare path
        if (pos < VCAP) {
            int i = sw ? qe : re, j = sw ? re : qe;
            g_viol[pos] = make_uint2(((unsigned int)i << 12) | (unsigned int)j,
                                     __float_as_uint(pl));
        }
    }
}

// grid = (CHNK, B). SMEM-staged; each block owns row-PAIRS (ki, ki+1) strided
// by 2*CHNK: one q-load serves two pairs (ILP x2, loads halved).
__global__ void __launch_bounds__(BLK)
compute_kernel(float* __restrict__ out, int E, int writeBig, int totBlocks) {
    __shared__ float4 sP[SMAXL];
    __shared__ float4 sM[SMAXL];
    __shared__ float4 sD[SMAXL];

    const int b = blockIdx.y;
    const int c = blockIdx.x;
    const int L = min(g_bk.bcnt[b], MAXE);
    const bool inSmem = (L <= SMAXL);
    const int lane = threadIdx.x & 31;

    const float4* __restrict__ P = inSmem ? sP : (g_tP + b * MAXE);
    const float4* __restrict__ M = inSmem ? sM : (g_tM + b * MAXE);
    const float4* __restrict__ D = inSmem ? sD : (g_tD + b * MAXE);

    if (inSmem) {
        for (int k = threadIdx.x; k < L; k += BLK) {
            int o = b * MAXE + k;
            sP[k] = g_tP[o]; sM[k] = g_tM[o]; sD[k] = g_tD[o];
        }
        __syncthreads();
    }

    float* __restrict__ outM = out + 1;
    float* __restrict__ outS = out + 1 + (size_t)E * (size_t)E;

    unsigned long long accQ = 0ull;
    unsigned int       cnt  = 0u;

    for (int ki = 2 * c; ki < L; ki += 2 * CHNK) {
        // Row 0 = ki, Row 1 = ki+1 (may be out of range)
        bool ok1 = (ki + 1) < L;
        int k1 = ok1 ? (ki + 1) : ki;
        float4 r0P = P[ki], r0M = M[ki], r0D = D[ki];
        float4 r1P = P[k1], r1M = M[k1], r1D = D[k1];
        unsigned int p0 = __float_as_uint(r0M.w);
        unsigned int p1 = __float_as_uint(r1M.w);
        int e0 = __float_as_int(r0D.w);
        int e1 = __float_as_int(r1D.w);

        for (int kj = ki + 1 + threadIdx.x; kj < L; kj += BLK) {
            float4 qP = P[kj], qM = M[kj], qD = D[kj];
            unsigned int pq = __float_as_uint(qM.w);
            int qe = __float_as_int(qD.w);

            bool sw0, sw1;
            float pl0 = pair_eval(r0P, r0M, r0D, p0, e0,
                                  qP, qM, qD, pq, qe, true, &cnt, &sw0);
            float pl1 = pair_eval(r1P, r1M, r1D, p1, e1,
                                  qP, qM, qD, pq, qe,
                                  ok1 && (kj > ki + 1), &cnt, &sw1);
            record_hit(pl0, sw0, e0, qe, &accQ);
            record_hit(pl1, sw1, e1, qe, &accQ);
        }
    }

    // Uniform reduction -> global integer totals
#pragma unroll
    for (int o = 16; o; o >>= 1) {
        accQ += __shfl_xor_sync(0xffffffffu, accQ, o);
        cnt  += __shfl_xor_sync(0xffffffffu, cnt,  o);
    }
    __shared__ unsigned long long rQ[BLK / 32];
    __shared__ unsigned int       rC[BLK / 32];
    int w = threadIdx.x >> 5;
    if (lane == 0) { rQ[w] = accQ; rC[w] = cnt; }
    __syncthreads();
    __shared__ unsigned int sLast;
    if (threadIdx.x == 0) {
        unsigned long long q = 0ull; unsigned int cc = 0u;
#pragma unroll
        for (int k = 0; k < BLK / 32; k++) { q += rQ[k]; cc += rC[k]; }
        if (q) atomicAdd(&g_bk.totQ, q);
        if (cc) atomicAdd(&g_bk.totC, (unsigned long long)cc);
        __threadfence();
        sLast = (atomicAdd(&g_bk.done, 1u) == (unsigned int)totBlocks - 1u);
    }
    __syncthreads();

    // Last block: loss + scatter + self-reset bookkeeping for next replay
    if (sLast) {
        __threadfence();   // all other blocks' stores visible
        unsigned int nv = min(g_bk.nViol, (unsigned int)VCAP);
        if (threadIdx.x == 0) {
            double sum = (double)g_bk.totQ * (1.0 / 1099511627776.0);
            unsigned long long n = g_bk.totC ? g_bk.totC : 1ull;
            out[0] = (float)(sum / (double)n);
        }
        if (writeBig) {
            for (unsigned int k = threadIdx.x; k < nv; k += BLK) {
                uint2 v = g_viol[k];
                int i = (int)(v.x >> 12);
                int j = (int)(v.x & 0xFFFu);
                size_t off = (size_t)i * (size_t)E + (size_t)j;
                outM[off] = 1.0f;
                outS[off] = __uint_as_float(v.y);
            }
        }
        __syncthreads();
        if (threadIdx.x == 0) {
            g_bk.totQ = 0ull; g_bk.totC = 0ull;
            g_bk.nViol = 0u;  g_bk.done = 0u;
        }
        if (threadIdx.x < MAXB) g_bk.bcnt[threadIdx.x] = 0;
    }
}

extern "C" void kernel_launch(void* const* d_in, const int* in_sizes, int n_in,
                              void* d_out, int out_size) {
    const float* pos = (const float*)d_in[0];
    // d_in[1] = adjacency: unused by the reference computation
    const int*   ei  = (const int*)d_in[2];

    int E     = in_sizes[2] / 2;
    int nodes = in_sizes[0] / 2;
    int N     = in_sizes[1] / nodes;
    int B     = min((nodes + N - 1) / N, MAXB);

    long long need = 1ll + 2ll * (long long)E * (long long)E;
    int writeBig = ((long long)out_size >= need) ? 1 : 0;

    float* out = (float*)d_out;

    // 1) Zero-fill output planes (driver memset: streaming write rate)
    if (writeBig) {
        cudaMemsetAsync(out + 1, 0,
                        2ull * (size_t)E * (size_t)E * sizeof(float));
    } else if (out_size > 1) {
        cudaMemsetAsync(out + 1, 0, ((size_t)out_size - 1) * sizeof(float));
    }

    // 2) Batch-major tables (block-aggregated batching atomics)
    prep_kernel<<<(E + BLK - 1) / BLK, BLK>>>(pos, ei, E, N, nodes);

    // 3) Row-pair tiled compute; last block scatters + loss + self-reset
    dim3 grid(CHNK, B);
    compute_kernel<<<grid, BLK>>>(out, E, writeBig, CHNK * B);
}

// round 17
// speedup vs baseline: 8.8040x; 8.8040x over previous
#include <cuda_runtime.h>
#include <cuda_bf16.h>
#include <cstdint>

// ---------------------------------------------------------------------------
// SpatialNonIntersectionAxiom — serial 4-node graph:
//   memset(bk+slots) -> memset(planes) -> prep -> compute.
// Compute = R10's proven SMEM-staged branchless body (18.3us) with the
// same-address atomic tail removed via per-block accumulator slots.
// out[0]=loss, out[1..1+E^2)=violation_mask, out[1+E^2..1+2E^2)=scores (f32).
// Integer fixed-point (2^-40) totals -> bit-deterministic across replays.
// Rules learned: no warp collectives in non-uniform loops; no fill/compute
// co-residency; no structure changes that grow the live set (spill cliff).
// ---------------------------------------------------------------------------

#define MAXE  8192
#define MAXB  16
#define BLK   256
#define CHNK  48
#define SMAXL 768
#define NSLOT 1024

// Batch-major per-edge tables (__device__: no allocs allowed)
__device__ float4 g_tP[MAXB * MAXE]; // psx, psy, d1x, d1y
__device__ float4 g_tM[MAXB * MAXE]; // midx, midy, hh=half+0.075, packed(s<<12|d)
__device__ float4 g_tD[MAXB * MAXE]; // dda, sq(clamped), rinv=1/sq, edgeIdx bits

struct Bookkeep {
    unsigned int done;                 // finished-block counter
    unsigned int pad;
    int bcnt[MAXB];                    // per-batch table lengths
    unsigned long long slotQ[NSLOT];   // per-block fixed-point loss sums
    unsigned int       slotC[NSLOT];   // per-block candidate counts
};
__device__ Bookkeep g_bk;

__global__ void __launch_bounds__(BLK)
prep_kernel(const float* __restrict__ pos, const int* __restrict__ ei,
            int E, int N, int nodes) {
    __shared__ int scnt[MAXB];
    __shared__ int sbase[MAXB];
    if (threadIdx.x < MAXB) scnt[threadIdx.x] = 0;
    __syncthreads();

    int e = blockIdx.x * blockDim.x + threadIdx.x;
    int b = 0, lslot = 0, s = 0, d = 0;
    bool valid = (e < E);
    if (valid) {
        s = min(max(ei[e], 0), nodes - 1);
        d = min(max(ei[E + e], 0), nodes - 1);
        b = min(s / N, MAXB - 1);
        lslot = atomicAdd(&scnt[b], 1);           // smem atomic: cheap
    }
    __syncthreads();
    if (threadIdx.x < MAXB)                        // 1 global atomic per batch
        sbase[threadIdx.x] = atomicAdd(&g_bk.bcnt[threadIdx.x],
                                       scnt[threadIdx.x]);
    __syncthreads();

    if (valid) {
        int p = sbase[b] + lslot;
        if (p < MAXE) {
            float psx = pos[2 * s], psy = pos[2 * s + 1];
            float pdx = pos[2 * d], pdy = pos[2 * d + 1];
            float d1x = pdx - psx,  d1y = pdy - psy;
            float rawsq = d1x * d1x + d1y * d1y;
            float sq    = fmaxf(rawsq, 1e-12f);
            float rinv  = __fdiv_rn(1.0f, sq);
            float half  = __fsqrt_rn(rawsq) * 0.5f;
            unsigned int packed = (((unsigned int)s & 0xFFFu) << 12)
                                | ((unsigned int)d & 0xFFFu);
            int o = b * MAXE + p;
            g_tP[o] = make_float4(psx, psy, d1x, d1y);
            g_tM[o] = make_float4((psx + pdx) * 0.5f, (psy + pdy) * 0.5f,
                                  half + 0.075f, __uint_as_float(packed));
            g_tD[o] = make_float4(d1x * psx + d1y * psy, sq, rinv,
                                  __int_as_float(e));
        }
    }
}

// grid = (CHNK, B). R10's SMEM-staged branchless body verbatim; direct
// scatter; per-block slot accumulators; last block reduces slots -> out[0].
__global__ void __launch_bounds__(BLK)
compute_kernel(float* __restrict__ out, int E, int writeBig, int totBlocks) {
    __shared__ float4 sP[SMAXL];
    __shared__ float4 sM[SMAXL];
    __shared__ float4 sD[SMAXL];

    const int b = blockIdx.y;
    const int c = blockIdx.x;
    const int L = min(g_bk.bcnt[b], MAXE);
    const bool inSmem = (L <= SMAXL);
    const int lane = threadIdx.x & 31;
    const int blockId = b * CHNK + c;

    const float4* __restrict__ P = inSmem ? sP : (g_tP + b * MAXE);
    const float4* __restrict__ M = inSmem ? sM : (g_tM + b * MAXE);
    const float4* __restrict__ D = inSmem ? sD : (g_tD + b * MAXE);

    if (inSmem) {
        for (int k = threadIdx.x; k < L; k += BLK) {
            int o = b * MAXE + k;
            sP[k] = g_tP[o]; sM[k] = g_tM[o]; sD[k] = g_tD[o];
        }
        __syncthreads();
    }

    float* __restrict__ outM = out + 1;
    float* __restrict__ outS = out + 1 + (size_t)E * (size_t)E;

    unsigned long long accQ = 0ull;
    unsigned int       cnt  = 0u;

    for (int ki = c; ki < L; ki += CHNK) {
        float4 rP = P[ki], rM = M[ki], rD = D[ki];
        unsigned int pr = __float_as_uint(rM.w);
        unsigned int rs = pr >> 12, rd = pr & 0xFFFu;
        int re = __float_as_int(rD.w);

        for (int kj = ki + 1 + threadIdx.x; kj < L; kj += BLK) {
            float4 qM = M[kj];
            float4 qP = P[kj];
            float4 qD = D[kj];
            unsigned int pq = __float_as_uint(qM.w);
            unsigned int qs = pq >> 12, qd = pq & 0xFFFu;
            bool shares = (rs == qs) | (rs == qd) | (rd == qs) | (rd == qd);
            float dx = rM.x - qM.x;
            float dy = rM.y - qM.y;
            float d2 = dx * dx + dy * dy;
            float reach = rM.z + qM.z;            // half_i+half_j+0.15
            bool maskok = (!shares) && (d2 < reach * reach);
            cnt += maskok ? 1u : 0u;

            // Branchless segment distance (orient i = smaller edge index)
            int qe = __float_as_int(qD.w);
            bool sw = re > qe;
            float iAx = sw ? qP.x : rP.x, iAy = sw ? qP.y : rP.y;
            float iAz = sw ? qP.z : rP.z, iAw = sw ? qP.w : rP.w;
            float jAx = sw ? rP.x : qP.x, jAy = sw ? rP.y : qP.y;
            float jAz = sw ? rP.z : qP.z, jAw = sw ? rP.w : qP.w;
            float iDd = sw ? qD.x : rD.x, jDd = sw ? rD.x : qD.x;
            float A   = sw ? qD.y : rD.y, Ee  = sw ? rD.y : qD.y;
            float rA  = sw ? qD.z : rD.z, rE  = sw ? rD.z : qD.z;

            float bb = iAz * jAz + iAw * jAw;
            float cc = iDd - (iAz * jAx + iAw * jAy);
            float ff = (iAx * jAz + iAy * jAw) - jDd;
            float denom = fmaxf(A * Ee - bb * bb, 1e-12f);
            float s = (bb * ff - cc * Ee) * __frcp_rn(denom);
            s = fminf(fmaxf(s, 0.0f), 1.0f);
            float t = fminf(fmaxf((bb * s + ff) * rE, 0.0f), 1.0f);
            s = fminf(fmaxf((bb * t - cc) * rA, 0.0f), 1.0f);
            float cax = iAx + s * iAz;
            float cay = iAy + s * iAw;
            float cbx = jAx + t * jAz;
            float cby = jAy + t * jAw;
            float ddx = cax - cbx, ddy = cay - cby;
            float dmsq = ddx * ddx + ddy * ddy;

            if (maskok && dmsq < 1.01e-6f) {      // rare: real violations
                float dmin = __fsqrt_rn(dmsq);
                float pl = 0.001f - dmin;
                if (pl > 0.0f) {
                    accQ += (unsigned long long)
                        __double2ll_rn((double)pl * 1099511627776.0);
                    if (writeBig) {
                        int i = sw ? qe : re, j = sw ? re : qe;
                        size_t off = (size_t)i * (size_t)E + (size_t)j;
                        outM[off] = 1.0f;         // mask & (pair_loss > 0)
                        outS[off] = pl;           // pair_loss
                    }
                }
            }
        }
    }

    // Uniform reduction -> per-block slots (distinct addresses: no serialize)
#pragma unroll
    for (int o = 16; o; o >>= 1) {
        accQ += __shfl_xor_sync(0xffffffffu, accQ, o);
        cnt  += __shfl_xor_sync(0xffffffffu, cnt,  o);
    }
    __shared__ unsigned long long rQ[BLK / 32];
    __shared__ unsigned int       rC[BLK / 32];
    int w = threadIdx.x >> 5;
    if (lane == 0) { rQ[w] = accQ; rC[w] = cnt; }
    __syncthreads();
    __shared__ unsigned int sLast;
    if (threadIdx.x == 0) {
        unsigned long long q = 0ull; unsigned int cc = 0u;
#pragma unroll
        for (int k = 0; k < BLK / 32; k++) { q += rQ[k]; cc += rC[k]; }
        g_bk.slotQ[blockId] = q;                  // plain stores, no atomics
        g_bk.slotC[blockId] = cc;
        __threadfence();
        sLast = (atomicAdd(&g_bk.done, 1u) == (unsigned int)totBlocks - 1u);
    }
    __syncthreads();

    // Last block: block-wide slot reduction -> out[0]
    if (sLast) {
        __threadfence();   // all other blocks' slot stores visible
        unsigned long long q = 0ull, cc = 0ull;
        for (int k = threadIdx.x; k < totBlocks; k += BLK) {
            q  += g_bk.slotQ[k];
            cc += (unsigned long long)g_bk.slotC[k];
        }
#pragma unroll
        for (int o = 16; o; o >>= 1) {
            q  += __shfl_xor_sync(0xffffffffu, q,  o);
            cc += __shfl_xor_sync(0xffffffffu, cc, o);
        }
        __shared__ unsigned long long fQ[BLK / 32];
        __shared__ unsigned long long fC[BLK / 32];
        if (lane == 0) { fQ[w] = q; fC[w] = cc; }
        __syncthreads();
        if (threadIdx.x == 0) {
            unsigned long long tq = 0ull, tc = 0ull;
#pragma unroll
            for (int k = 0; k < BLK / 32; k++) { tq += fQ[k]; tc += fC[k]; }
            double sum = (double)tq * (1.0 / 1099511627776.0);
            unsigned long long n = tc ? tc : 1ull;
            out[0] = (float)(sum / (double)n);
        }
    }
}

extern "C" void kernel_launch(void* const* d_in, const int* in_sizes, int n_in,
                              void* d_out, int out_size) {
    const float* pos = (const float*)d_in[0];
    // d_in[1] = adjacency: unused by the reference computation
    const int*   ei  = (const int*)d_in[2];

    int E     = in_sizes[2] / 2;
    int nodes = in_sizes[0] / 2;
    int N     = in_sizes[1] / nodes;
    int B     = min((nodes + N - 1) / N, MAXB);

    long long need = 1ll + 2ll * (long long)E * (long long)E;
    int writeBig = ((long long)out_size >= need) ? 1 : 0;

    float* out = (float*)d_out;

    // 1) Clear bookkeeping (done, bcnt, used slot range)
    void* bkPtr = nullptr;
    cudaGetSymbolAddress(&bkPtr, g_bk);
    cudaMemsetAsync(bkPtr, 0, sizeof(Bookkeep));

    // 2) Zero-fill output planes (driver memset: streaming write rate)
    if (writeBig) {
        cudaMemsetAsync(out + 1, 0,
                        2ull * (size_t)E * (size_t)E * sizeof(float));
    } else if (out_size > 1) {
        cudaMemsetAsync(out + 1, 0, ((size_t)out_size - 1) * sizeof(float));
    }

    // 3) Batch-major tables (block-aggregated batching atomics)
    prep_kernel<<<(E + BLK - 1) / BLK, BLK>>>(pos, ei, E, N, nodes);

    // 4) Pair compute + direct scatter + last-block loss
    dim3 grid(CHNK, B);
    compute_kernel<<<grid, BLK>>>(out, E, writeBig, CHNK * B);
}